// round 6
// baseline (speedup 1.0000x reference)
#include <cuda_runtime.h>
#include <math.h>

// ---------------------------------------------------------------------------
// Round 6: prologue kernel pre-packs ALL weights into MMA B-fragment order
// (tf32, padded) in __device__ buffers. Main kernel: zero weight staging,
// zero inter-phase barriers; B-fragments via coalesced LDG (L1-resident).
// Expert-out layer is an MMA too (block-diagonal We2, N=16).
// smem 15KB static, ~6-8 CTAs/SM.
// Output: [action B*6 | vf B*128 | expout B*12] fp32.
// ---------------------------------------------------------------------------

static constexpr int ROWS = 128;
static constexpr int TPB  = 256;

// packed weight buffers: [(kc*NT+nt)*32 + lane] -> {b0,b1}
__device__ float2 g_Ws0p[16 * 16 * 32];  // K=128,N=128
__device__ float2 g_Ws1p[16 *  8 * 32];  // K=128,N=64  (62 valid)
__device__ float2 g_Wvp [ 8 * 16 * 32];  // K=64(62),N=128
__device__ float2 g_We1p[ 8 * 16 * 32];  // K=64(62),N=128 (concat experts)
__device__ float2 g_Gp  [ 8 *  1 * 32];  // K=64(62),N=8 (gate0,gate1,noise0,noise1)
__device__ float2 g_W2p [16 *  2 * 32];  // K=128,N=16 (block-diag We2, 12 valid)

__device__ __forceinline__ unsigned f2tf_u(float x) {
    unsigned u; asm("cvt.rna.tf32.f32 %0, %1;" : "=r"(u) : "f"(x)); return u;
}
__device__ __forceinline__ float tf(float x) { return __uint_as_float(f2tf_u(x)); }

__device__ __forceinline__ float tanh_fast(float x) {
    float e = __expf(2.0f * x);
    return 1.0f - 2.0f * (1.0f / (e + 1.0f));
}
__device__ __forceinline__ float softplus_fast(float x) {
    return fmaxf(x, 0.f) + log1pf(__expf(-fabsf(x)));
}

// ============================ prologue =======================================
__global__ void pack_weights(const float* __restrict__ Ws0,
                             const float* __restrict__ Ws1,
                             const float* __restrict__ Wv,
                             const float* __restrict__ We1,
                             const float* __restrict__ wg,
                             const float* __restrict__ wn,
                             const float* __restrict__ We2) {
    int idx = blockIdx.x * blockDim.x + threadIdx.x;
    int lane = idx & 31, r = lane >> 2, c = lane & 3;

    if (idx < 8192) {                       // Ws0p: KC=16, NT=16
        int t = idx >> 5, nt = t & 15, kc = t >> 4;
        int n = nt * 8 + r, k0 = kc * 8 + c;
        g_Ws0p[idx] = make_float2(tf(Ws0[k0 * 128 + n]), tf(Ws0[(k0 + 4) * 128 + n]));
    } else if (idx < 12288) {               // Ws1p: KC=16, NT=8
        int i = idx - 8192;
        int t = i >> 5, nt = t & 7, kc = t >> 3;
        int n = nt * 8 + r, k0 = kc * 8 + c;
        float v0 = (n < 62) ? tf(Ws1[k0 * 62 + n])       : 0.f;
        float v1 = (n < 62) ? tf(Ws1[(k0 + 4) * 62 + n]) : 0.f;
        g_Ws1p[i] = make_float2(v0, v1);
    } else if (idx < 16384) {               // Wvp: KC=8, NT=16
        int i = idx - 12288;
        int t = i >> 5, nt = t & 15, kc = t >> 4;
        int n = nt * 8 + r, k0 = kc * 8 + c, k1 = k0 + 4;
        float v0 = (k0 < 62) ? tf(Wv[k0 * 128 + n]) : 0.f;
        float v1 = (k1 < 62) ? tf(Wv[k1 * 128 + n]) : 0.f;
        g_Wvp[i] = make_float2(v0, v1);
    } else if (idx < 20480) {               // We1p: KC=8, NT=16 (cols e*64+hid)
        int i = idx - 16384;
        int t = i >> 5, nt = t & 15, kc = t >> 4;
        int n = nt * 8 + r, k0 = kc * 8 + c, k1 = k0 + 4;
        int e = n >> 6, hid = n & 63;
        float v0 = (k0 < 62) ? tf(We1[((e * 62 + k0) << 6) + hid]) : 0.f;
        float v1 = (k1 < 62) ? tf(We1[((e * 62 + k1) << 6) + hid]) : 0.f;
        g_We1p[i] = make_float2(v0, v1);
    } else if (idx < 20736) {               // Gp: KC=8, NT=1, cols: g0,g1,n0,n1
        int i = idx - 20480;
        int kc = i >> 5;
        int n = r, k0 = kc * 8 + c, k1 = k0 + 4;
        float v0 = 0.f, v1 = 0.f;
        if (n < 2)      { if (k0 < 62) v0 = tf(wg[k0 * 2 + n]);
                          if (k1 < 62) v1 = tf(wg[k1 * 2 + n]); }
        else if (n < 4) { if (k0 < 62) v0 = tf(wn[k0 * 2 + n - 2]);
                          if (k1 < 62) v1 = tf(wn[k1 * 2 + n - 2]); }
        g_Gp[i] = make_float2(v0, v1);
    } else if (idx < 21760) {               // W2p: KC=16, NT=2 (block-diag)
        int i = idx - 20736;
        int t = i >> 5, nt = t & 1, kc = t >> 1;
        int n = nt * 8 + r, k0 = kc * 8 + c, k1 = k0 + 4;
        float v0 = 0.f, v1 = 0.f;
        if (n < 12) {
            int e = n / 6, o = n - e * 6;
            if ((k0 >> 6) == e) v0 = tf(We2[k0 * 6 + o]);
            if ((k1 >> 6) == e) v1 = tf(We2[k1 * 6 + o]);
        }
        g_W2p[i] = make_float2(v0, v1);
    }
}

// ============================ main kernel helpers ============================
__device__ __forceinline__ void mma8(float d[4], unsigned a0, unsigned a1,
                                     unsigned a2, unsigned a3,
                                     unsigned b0, unsigned b1) {
    asm("mma.sync.aligned.m16n8k8.row.col.f32.tf32.tf32.f32 "
        "{%0,%1,%2,%3},{%4,%5,%6,%7},{%8,%9},{%0,%1,%2,%3};"
        : "+f"(d[0]), "+f"(d[1]), "+f"(d[2]), "+f"(d[3])
        : "r"(a0), "r"(a1), "r"(a2), "r"(a3), "r"(b0), "r"(b1));
}

// m16n8 output frag (d0=(r,2c),d1=(r,2c+1),d2=(r+8,2c),d3=(r+8,2c+1)) ->
// tf32 A frag (a0=(r,c),a1=(r+8,c),a2=(r,c+4),a3=(r+8,c+4)), in place.
__device__ __forceinline__ void frag_to_a(float (&d)[4], int lane) {
    int base = lane & ~3;
    int src  = base | ((lane & 3) >> 1);
    float v0 = __shfl_sync(0xffffffffu, d[0], src);
    float v1 = __shfl_sync(0xffffffffu, d[1], src);
    float v2 = __shfl_sync(0xffffffffu, d[2], src);
    float v3 = __shfl_sync(0xffffffffu, d[3], src);
    float w0 = __shfl_sync(0xffffffffu, d[0], src + 2);
    float w1 = __shfl_sync(0xffffffffu, d[1], src + 2);
    float w2 = __shfl_sync(0xffffffffu, d[2], src + 2);
    float w3 = __shfl_sync(0xffffffffu, d[3], src + 2);
    bool odd = lane & 1;
    d[0] = odd ? v1 : v0;
    d[1] = odd ? v3 : v2;
    d[2] = odd ? w1 : w0;
    d[3] = odd ? w3 : w2;
}

// acc[NT] += A(frags) * B(packed gmem panel)
template <int KC, int NT, int UNR>
__device__ __forceinline__ void mma_panel_g(const float2* __restrict__ Wp,
                                            const float (&a)[KC][4],
                                            float (&acc)[NT][4], int lane) {
#pragma unroll UNR
    for (int kc = 0; kc < KC; kc++) {
        unsigned a0 = __float_as_uint(a[kc][0]);
        unsigned a1 = __float_as_uint(a[kc][1]);
        unsigned a2 = __float_as_uint(a[kc][2]);
        unsigned a3 = __float_as_uint(a[kc][3]);
        const float2* wp = Wp + kc * NT * 32 + lane;
#pragma unroll
        for (int nt = 0; nt < NT; nt++) {
            float2 b = __ldg(wp + nt * 32);
            mma8(acc[nt], a0, a1, a2, a3,
                 __float_as_uint(b.x), __float_as_uint(b.y));
        }
    }
}

template <int NT> __device__ __forceinline__ void zacc(float (&acc)[NT][4]) {
#pragma unroll
    for (int i = 0; i < NT; i++)
#pragma unroll
        for (int j = 0; j < 4; j++) acc[i][j] = 0.f;
}

struct f2 { union { unsigned long long u; float2 v; }; };

// ============================ main kernel ====================================
__global__ void __launch_bounds__(TPB) mlp_fused_kernel(
    const float* __restrict__ feat,   const float* __restrict__ noise,
    const float* __restrict__ bs0,    const float* __restrict__ bs1,
    const float* __restrict__ bv,     const float* __restrict__ be1,
    const float* __restrict__ be2,
    float* __restrict__ out_action, float* __restrict__ out_vf,
    float* __restrict__ out_expout)
{
    __shared__ float sLg[128 * 16];   // expert logits
    __shared__ float sG[256];         // gates [128][2]
    __shared__ float sAct[128 * 12];  // gate*expout

    const int tid  = threadIdx.x;
    const int lane = tid & 31;
    const int wrow = (tid >> 5) * 16;
    const int r = lane >> 2, c = lane & 3;
    const int row0 = blockIdx.x * ROWS;

    // ================= Phase A: h = tanh(feat @ Ws0 + bs0), N=128 ==========
    float hA[16][4];
    zacc(hA);
    {
        const float* fb  = feat + (size_t)(row0 + wrow + r) * 128 + c;
        const float* fb8 = fb + 8 * 128;
#pragma unroll 4
        for (int kc = 0; kc < 16; kc++) {
            unsigned a0 = f2tf_u(fb[kc * 8]);
            unsigned a1 = f2tf_u(fb8[kc * 8]);
            unsigned a2 = f2tf_u(fb[kc * 8 + 4]);
            unsigned a3 = f2tf_u(fb8[kc * 8 + 4]);
            const float2* wp = g_Ws0p + kc * 16 * 32 + lane;
#pragma unroll
            for (int nt = 0; nt < 16; nt++) {
                float2 b = __ldg(wp + nt * 32);
                mma8(hA[nt], a0, a1, a2, a3,
                     __float_as_uint(b.x), __float_as_uint(b.y));
            }
        }
#pragma unroll
        for (int nt = 0; nt < 16; nt++) {
            float2 bb = *(const float2*)&bs0[nt * 8 + 2 * c];
            hA[nt][0] = tf(tanh_fast(hA[nt][0] + bb.x));
            hA[nt][1] = tf(tanh_fast(hA[nt][1] + bb.y));
            hA[nt][2] = tf(tanh_fast(hA[nt][2] + bb.x));
            hA[nt][3] = tf(tanh_fast(hA[nt][3] + bb.y));
            frag_to_a(hA[nt], lane);
        }
    }

    // ================= Phase B: latent = tanh(h @ Ws1 + bs1), N=64 =========
    float la[8][4];
    zacc(la);
    mma_panel_g<16, 8, 4>(g_Ws1p, hA, la, lane);
#pragma unroll
    for (int nt = 0; nt < 8; nt++) {
        int col = nt * 8 + 2 * c;
        float bx = (col < 62)     ? bs1[col]     : 0.f;
        float by = (col + 1 < 62) ? bs1[col + 1] : 0.f;
        la[nt][0] = tf(tanh_fast(la[nt][0] + bx));
        la[nt][1] = tf(tanh_fast(la[nt][1] + by));
        la[nt][2] = tf(tanh_fast(la[nt][2] + bx));
        la[nt][3] = tf(tanh_fast(la[nt][3] + by));
        frag_to_a(la[nt], lane);
    }

    // ============ Gating via MMA against g_Gp (N=8) ========================
    {
        float g[1][4];
        zacc(g);
        mma_panel_g<8, 1, 8>(g_Gp, la, g, lane);
        int base = lane & ~3;
        float v00 = __shfl_sync(0xffffffffu, g[0][0], base);
        float v01 = __shfl_sync(0xffffffffu, g[0][1], base);
        float v10 = __shfl_sync(0xffffffffu, g[0][0], base + 1);
        float v11 = __shfl_sync(0xffffffffu, g[0][1], base + 1);
        float v20 = __shfl_sync(0xffffffffu, g[0][2], base);
        float v21 = __shfl_sync(0xffffffffu, g[0][3], base);
        float v30 = __shfl_sync(0xffffffffu, g[0][2], base + 1);
        float v31 = __shfl_sync(0xffffffffu, g[0][3], base + 1);
        if (c < 2) {
            float cl0 = (c == 0) ? v00 : v20;
            float cl1 = (c == 0) ? v01 : v21;
            float n0  = (c == 0) ? v10 : v30;
            float n1  = (c == 0) ? v11 : v31;
            int row = wrow + r + ((c == 0) ? 0 : 8);
            float2 nz = *(const float2*)&noise[(size_t)(row0 + row) * 2];
            float s0 = softplus_fast(n0) + 1e-2f;
            float s1 = softplus_fast(n1) + 1e-2f;
            float z0 = fmaf(nz.x, s0, cl0);
            float z1 = fmaf(nz.y, s1, cl1);
            float mx = fmaxf(z0, z1);
            float e0 = __expf(z0 - mx), e1 = __expf(z1 - mx);
            float inv = 1.f / (e0 + e1);
            sG[2 * row + 0] = e0 * inv;
            sG[2 * row + 1] = e1 * inv;
        }
    }

    // ============ Phase C: latent_vf = tanh(latent @ Wv + bv), N=128 =======
    {
        float acc[16][4];
        zacc(acc);
        mma_panel_g<8, 16, 8>(g_Wvp, la, acc, lane);
#pragma unroll
        for (int nt = 0; nt < 16; nt++) {
            int col = nt * 8 + 2 * c;
            float2 bb = *(const float2*)&bv[col];
            float2 lo, hi;
            lo.x = tanh_fast(acc[nt][0] + bb.x);
            lo.y = tanh_fast(acc[nt][1] + bb.y);
            hi.x = tanh_fast(acc[nt][2] + bb.x);
            hi.y = tanh_fast(acc[nt][3] + bb.y);
            *(float2*)&out_vf[(size_t)(row0 + wrow + r) * 128 + col]     = lo;
            *(float2*)&out_vf[(size_t)(row0 + wrow + r + 8) * 128 + col] = hi;
        }
    }

    // ========= Phase E: eh = relu(latent @ We1 + be1), N=128 ===============
    float ehA[16][4];
    zacc(ehA);
    mma_panel_g<8, 16, 8>(g_We1p, la, ehA, lane);
#pragma unroll
    for (int nt = 0; nt < 16; nt++) {
        int col = nt * 8 + 2 * c;
        float2 bb = *(const float2*)&be1[col];
        ehA[nt][0] = tf(fmaxf(ehA[nt][0] + bb.x, 0.f));
        ehA[nt][1] = tf(fmaxf(ehA[nt][1] + bb.y, 0.f));
        ehA[nt][2] = tf(fmaxf(ehA[nt][2] + bb.x, 0.f));
        ehA[nt][3] = tf(fmaxf(ehA[nt][3] + bb.y, 0.f));
        frag_to_a(ehA[nt], lane);
    }

    // ========= Phase F1: logits = eh @ blockdiag(We2) + be2, N=16 ==========
    {
        float lg[2][4];
        zacc(lg);
        mma_panel_g<16, 2, 4>(g_W2p, ehA, lg, lane);
#pragma unroll
        for (int nt = 0; nt < 2; nt++) {
            int col = nt * 8 + 2 * c;
            float bx = (col < 12)     ? be2[col]     : 0.f;
            float by = (col + 1 < 12) ? be2[col + 1] : 0.f;
            *(float2*)&sLg[(wrow + r) * 16 + col] =
                make_float2(lg[nt][0] + bx, lg[nt][1] + by);
            *(float2*)&sLg[(wrow + r + 8) * 16 + col] =
                make_float2(lg[nt][2] + bx, lg[nt][3] + by);
        }
    }
    __syncthreads();

    // ========= Phase F2: softmax + gated combine (thread=(row,e)) ==========
    {
        int row = tid >> 1, e = tid & 1;
        const float* lp = &sLg[row * 16 + e * 6];
        float lgs[6];
#pragma unroll
        for (int o = 0; o < 6; o++) lgs[o] = lp[o];
        float m = lgs[0];
#pragma unroll
        for (int o = 1; o < 6; o++) m = fmaxf(m, lgs[o]);
        float p[6], s = 0.f;
#pragma unroll
        for (int o = 0; o < 6; o++) { p[o] = __expf(lgs[o] - m); s += p[o]; }
        float inv = 1.f / s;
        float g = sG[tid];
        size_t gbase = ((size_t)(row0 + row) * 2 + e) * 6;
#pragma unroll
        for (int o = 0; o < 6; o++) {
            float po = p[o] * inv;
            out_expout[gbase + o] = po;
            sAct[tid * 6 + o] = g * po;
        }
    }
    __syncthreads();
    if (tid < 128) {
        size_t gbase = (size_t)(row0 + tid) * 6;
#pragma unroll
        for (int o = 0; o < 6; o++)
            out_action[gbase + o] = sAct[tid * 12 + o] + sAct[tid * 12 + 6 + o];
    }
}

extern "C" void kernel_launch(void* const* d_in, const int* in_sizes, int n_in,
                              void* d_out, int out_size) {
    const float* feat    = (const float*)d_in[0];
    const float* noise   = (const float*)d_in[1];
    const float* Ws0     = (const float*)d_in[2];
    const float* bs0     = (const float*)d_in[3];
    const float* Ws1     = (const float*)d_in[4];
    const float* bs1     = (const float*)d_in[5];
    const float* Wv      = (const float*)d_in[6];
    const float* bv      = (const float*)d_in[7];
    const float* w_gate  = (const float*)d_in[8];
    const float* w_noise = (const float*)d_in[9];
    const float* We1     = (const float*)d_in[10];
    const float* be1     = (const float*)d_in[11];
    const float* We2     = (const float*)d_in[12];
    const float* be2     = (const float*)d_in[13];

    const int B = in_sizes[0] / 128;

    float* out        = (float*)d_out;
    float* out_action = out;                       // [B,6]
    float* out_vf     = out + (size_t)B * 6;       // [B,128]
    float* out_expout = out + (size_t)B * 134;     // [B,2,6]

    pack_weights<<<85, 256>>>(Ws0, Ws1, Wv, We1, w_gate, w_noise, We2);
    mlp_fused_kernel<<<B / ROWS, TPB>>>(
        feat, noise, bs0, bs1, bv, be1, be2,
        out_action, out_vf, out_expout);
}

// round 7
// speedup vs baseline: 1.0226x; 1.0226x over previous
#include <cuda_runtime.h>
#include <math.h>

// ---------------------------------------------------------------------------
// Round 7: R6 barrier-lean design + L1-pinned weights (evict_last), streaming
// output stores, shuffle-combined action (no sAct smem / no tail barrier).
// Prologue packs all weights into MMA B-fragment order (tf32, padded).
// Output: [action B*6 | vf B*128 | expout B*12] fp32.
// ---------------------------------------------------------------------------

static constexpr int ROWS = 128;
static constexpr int TPB  = 256;

// packed weight buffers: [(kc*NT+nt)*32 + lane] -> {b0,b1}
__device__ float2 g_Ws0p[16 * 16 * 32];  // K=128,N=128
__device__ float2 g_Ws1p[16 *  8 * 32];  // K=128,N=64  (62 valid)
__device__ float2 g_Wvp [ 8 * 16 * 32];  // K=64(62),N=128
__device__ float2 g_We1p[ 8 * 16 * 32];  // K=64(62),N=128 (concat experts)
__device__ float2 g_Gp  [ 8 *  1 * 32];  // K=64(62),N=8 (g0,g1,n0,n1)
__device__ float2 g_W2p [16 *  2 * 32];  // K=128,N=16 (block-diag We2)

__device__ __forceinline__ unsigned f2tf_u(float x) {
    unsigned u; asm("cvt.rna.tf32.f32 %0, %1;" : "=r"(u) : "f"(x)); return u;
}
__device__ __forceinline__ float tf(float x) { return __uint_as_float(f2tf_u(x)); }

__device__ __forceinline__ float tanh_fast(float x) {
    float e = __expf(2.0f * x);
    return 1.0f - 2.0f * (1.0f / (e + 1.0f));
}
__device__ __forceinline__ float softplus_fast(float x) {
    return fmaxf(x, 0.f) + log1pf(__expf(-fabsf(x)));
}

// L1-pinned weight fragment load
__device__ __forceinline__ float2 ldg_evl(const float2* p) {
    float2 v;
    asm("ld.global.nc.L1::evict_last.v2.f32 {%0,%1}, [%2];"
        : "=f"(v.x), "=f"(v.y) : "l"(p));
    return v;
}

// ============================ prologue =======================================
__global__ void pack_weights(const float* __restrict__ Ws0,
                             const float* __restrict__ Ws1,
                             const float* __restrict__ Wv,
                             const float* __restrict__ We1,
                             const float* __restrict__ wg,
                             const float* __restrict__ wn,
                             const float* __restrict__ We2) {
    int idx = blockIdx.x * blockDim.x + threadIdx.x;
    int lane = idx & 31, r = lane >> 2, c = lane & 3;

    if (idx < 8192) {                       // Ws0p: KC=16, NT=16
        int t = idx >> 5, nt = t & 15, kc = t >> 4;
        int n = nt * 8 + r, k0 = kc * 8 + c;
        g_Ws0p[idx] = make_float2(tf(Ws0[k0 * 128 + n]), tf(Ws0[(k0 + 4) * 128 + n]));
    } else if (idx < 12288) {               // Ws1p: KC=16, NT=8
        int i = idx - 8192;
        int t = i >> 5, nt = t & 7, kc = t >> 3;
        int n = nt * 8 + r, k0 = kc * 8 + c;
        float v0 = (n < 62) ? tf(Ws1[k0 * 62 + n])       : 0.f;
        float v1 = (n < 62) ? tf(Ws1[(k0 + 4) * 62 + n]) : 0.f;
        g_Ws1p[i] = make_float2(v0, v1);
    } else if (idx < 16384) {               // Wvp: KC=8, NT=16
        int i = idx - 12288;
        int t = i >> 5, nt = t & 15, kc = t >> 4;
        int n = nt * 8 + r, k0 = kc * 8 + c, k1 = k0 + 4;
        float v0 = (k0 < 62) ? tf(Wv[k0 * 128 + n]) : 0.f;
        float v1 = (k1 < 62) ? tf(Wv[k1 * 128 + n]) : 0.f;
        g_Wvp[i] = make_float2(v0, v1);
    } else if (idx < 20480) {               // We1p: KC=8, NT=16
        int i = idx - 16384;
        int t = i >> 5, nt = t & 15, kc = t >> 4;
        int n = nt * 8 + r, k0 = kc * 8 + c, k1 = k0 + 4;
        int e = n >> 6, hid = n & 63;
        float v0 = (k0 < 62) ? tf(We1[((e * 62 + k0) << 6) + hid]) : 0.f;
        float v1 = (k1 < 62) ? tf(We1[((e * 62 + k1) << 6) + hid]) : 0.f;
        g_We1p[i] = make_float2(v0, v1);
    } else if (idx < 20736) {               // Gp: KC=8, NT=1
        int i = idx - 20480;
        int kc = i >> 5;
        int n = r, k0 = kc * 8 + c, k1 = k0 + 4;
        float v0 = 0.f, v1 = 0.f;
        if (n < 2)      { if (k0 < 62) v0 = tf(wg[k0 * 2 + n]);
                          if (k1 < 62) v1 = tf(wg[k1 * 2 + n]); }
        else if (n < 4) { if (k0 < 62) v0 = tf(wn[k0 * 2 + n - 2]);
                          if (k1 < 62) v1 = tf(wn[k1 * 2 + n - 2]); }
        g_Gp[i] = make_float2(v0, v1);
    } else if (idx < 21760) {               // W2p: KC=16, NT=2 (block-diag)
        int i = idx - 20736;
        int t = i >> 5, nt = t & 1, kc = t >> 1;
        int n = nt * 8 + r, k0 = kc * 8 + c, k1 = k0 + 4;
        float v0 = 0.f, v1 = 0.f;
        if (n < 12) {
            int e = n / 6, o = n - e * 6;
            if ((k0 >> 6) == e) v0 = tf(We2[k0 * 6 + o]);
            if ((k1 >> 6) == e) v1 = tf(We2[k1 * 6 + o]);
        }
        g_W2p[i] = make_float2(v0, v1);
    }
}

// ============================ main kernel helpers ============================
__device__ __forceinline__ void mma8(float d[4], unsigned a0, unsigned a1,
                                     unsigned a2, unsigned a3,
                                     unsigned b0, unsigned b1) {
    asm("mma.sync.aligned.m16n8k8.row.col.f32.tf32.tf32.f32 "
        "{%0,%1,%2,%3},{%4,%5,%6,%7},{%8,%9},{%0,%1,%2,%3};"
        : "+f"(d[0]), "+f"(d[1]), "+f"(d[2]), "+f"(d[3])
        : "r"(a0), "r"(a1), "r"(a2), "r"(a3), "r"(b0), "r"(b1));
}

__device__ __forceinline__ void frag_to_a(float (&d)[4], int lane) {
    int base = lane & ~3;
    int src  = base | ((lane & 3) >> 1);
    float v0 = __shfl_sync(0xffffffffu, d[0], src);
    float v1 = __shfl_sync(0xffffffffu, d[1], src);
    float v2 = __shfl_sync(0xffffffffu, d[2], src);
    float v3 = __shfl_sync(0xffffffffu, d[3], src);
    float w0 = __shfl_sync(0xffffffffu, d[0], src + 2);
    float w1 = __shfl_sync(0xffffffffu, d[1], src + 2);
    float w2 = __shfl_sync(0xffffffffu, d[2], src + 2);
    float w3 = __shfl_sync(0xffffffffu, d[3], src + 2);
    bool odd = lane & 1;
    d[0] = odd ? v1 : v0;
    d[1] = odd ? v3 : v2;
    d[2] = odd ? w1 : w0;
    d[3] = odd ? w3 : w2;
}

template <int KC, int NT, int UNR>
__device__ __forceinline__ void mma_panel_g(const float2* __restrict__ Wp,
                                            const float (&a)[KC][4],
                                            float (&acc)[NT][4], int lane) {
#pragma unroll UNR
    for (int kc = 0; kc < KC; kc++) {
        unsigned a0 = __float_as_uint(a[kc][0]);
        unsigned a1 = __float_as_uint(a[kc][1]);
        unsigned a2 = __float_as_uint(a[kc][2]);
        unsigned a3 = __float_as_uint(a[kc][3]);
        const float2* wp = Wp + kc * NT * 32 + lane;
#pragma unroll
        for (int nt = 0; nt < NT; nt++) {
            float2 b = ldg_evl(wp + nt * 32);
            mma8(acc[nt], a0, a1, a2, a3,
                 __float_as_uint(b.x), __float_as_uint(b.y));
        }
    }
}

template <int NT> __device__ __forceinline__ void zacc(float (&acc)[NT][4]) {
#pragma unroll
    for (int i = 0; i < NT; i++)
#pragma unroll
        for (int j = 0; j < 4; j++) acc[i][j] = 0.f;
}

// ============================ main kernel ====================================
__global__ void __launch_bounds__(TPB, 2) mlp_fused_kernel(
    const float* __restrict__ feat,   const float* __restrict__ noise,
    const float* __restrict__ bs0,    const float* __restrict__ bs1,
    const float* __restrict__ bv,     const float* __restrict__ be1,
    const float* __restrict__ be2,
    float* __restrict__ out_action, float* __restrict__ out_vf,
    float* __restrict__ out_expout)
{
    __shared__ float sLg[128 * 16];   // expert logits
    __shared__ float sG[256];         // gates [128][2]

    const int tid  = threadIdx.x;
    const int lane = tid & 31;
    const int wrow = (tid >> 5) * 16;
    const int r = lane >> 2, c = lane & 3;
    const int row0 = blockIdx.x * ROWS;

    // ================= Phase A: h = tanh(feat @ Ws0 + bs0), N=128 ==========
    float hA[16][4];
    zacc(hA);
    {
        const float* fb  = feat + (size_t)(row0 + wrow + r) * 128 + c;
        const float* fb8 = fb + 8 * 128;
#pragma unroll 4
        for (int kc = 0; kc < 16; kc++) {
            unsigned a0 = f2tf_u(fb[kc * 8]);
            unsigned a1 = f2tf_u(fb8[kc * 8]);
            unsigned a2 = f2tf_u(fb[kc * 8 + 4]);
            unsigned a3 = f2tf_u(fb8[kc * 8 + 4]);
            const float2* wp = g_Ws0p + kc * 16 * 32 + lane;
#pragma unroll
            for (int nt = 0; nt < 16; nt++) {
                float2 b = ldg_evl(wp + nt * 32);
                mma8(hA[nt], a0, a1, a2, a3,
                     __float_as_uint(b.x), __float_as_uint(b.y));
            }
        }
#pragma unroll
        for (int nt = 0; nt < 16; nt++) {
            float2 bb = *(const float2*)&bs0[nt * 8 + 2 * c];
            hA[nt][0] = tf(tanh_fast(hA[nt][0] + bb.x));
            hA[nt][1] = tf(tanh_fast(hA[nt][1] + bb.y));
            hA[nt][2] = tf(tanh_fast(hA[nt][2] + bb.x));
            hA[nt][3] = tf(tanh_fast(hA[nt][3] + bb.y));
            frag_to_a(hA[nt], lane);
        }
    }

    // ================= Phase B: latent = tanh(h @ Ws1 + bs1), N=64 =========
    float la[8][4];
    zacc(la);
    mma_panel_g<16, 8, 4>(g_Ws1p, hA, la, lane);
#pragma unroll
    for (int nt = 0; nt < 8; nt++) {
        int col = nt * 8 + 2 * c;
        float bx = (col < 62)     ? bs1[col]     : 0.f;
        float by = (col + 1 < 62) ? bs1[col + 1] : 0.f;
        la[nt][0] = tf(tanh_fast(la[nt][0] + bx));
        la[nt][1] = tf(tanh_fast(la[nt][1] + by));
        la[nt][2] = tf(tanh_fast(la[nt][2] + bx));
        la[nt][3] = tf(tanh_fast(la[nt][3] + by));
        frag_to_a(la[nt], lane);
    }

    // ============ Gating via MMA against g_Gp (N=8) ========================
    {
        float g[1][4];
        zacc(g);
        mma_panel_g<8, 1, 8>(g_Gp, la, g, lane);
        int base = lane & ~3;
        float v00 = __shfl_sync(0xffffffffu, g[0][0], base);
        float v01 = __shfl_sync(0xffffffffu, g[0][1], base);
        float v10 = __shfl_sync(0xffffffffu, g[0][0], base + 1);
        float v11 = __shfl_sync(0xffffffffu, g[0][1], base + 1);
        float v20 = __shfl_sync(0xffffffffu, g[0][2], base);
        float v21 = __shfl_sync(0xffffffffu, g[0][3], base);
        float v30 = __shfl_sync(0xffffffffu, g[0][2], base + 1);
        float v31 = __shfl_sync(0xffffffffu, g[0][3], base + 1);
        if (c < 2) {
            float cl0 = (c == 0) ? v00 : v20;
            float cl1 = (c == 0) ? v01 : v21;
            float n0  = (c == 0) ? v10 : v30;
            float n1  = (c == 0) ? v11 : v31;
            int row = wrow + r + ((c == 0) ? 0 : 8);
            float2 nz = *(const float2*)&noise[(size_t)(row0 + row) * 2];
            float s0 = softplus_fast(n0) + 1e-2f;
            float s1 = softplus_fast(n1) + 1e-2f;
            float z0 = fmaf(nz.x, s0, cl0);
            float z1 = fmaf(nz.y, s1, cl1);
            float mx = fmaxf(z0, z1);
            float e0 = __expf(z0 - mx), e1 = __expf(z1 - mx);
            float inv = 1.f / (e0 + e1);
            sG[2 * row + 0] = e0 * inv;
            sG[2 * row + 1] = e1 * inv;
        }
    }

    // ============ Phase C: latent_vf = tanh(latent @ Wv + bv), N=128 =======
    {
        float acc[16][4];
        zacc(acc);
        mma_panel_g<8, 16, 8>(g_Wvp, la, acc, lane);
#pragma unroll
        for (int nt = 0; nt < 16; nt++) {
            int col = nt * 8 + 2 * c;
            float2 bb = *(const float2*)&bv[col];
            float2 lo, hi;
            lo.x = tanh_fast(acc[nt][0] + bb.x);
            lo.y = tanh_fast(acc[nt][1] + bb.y);
            hi.x = tanh_fast(acc[nt][2] + bb.x);
            hi.y = tanh_fast(acc[nt][3] + bb.y);
            __stcs((float2*)&out_vf[(size_t)(row0 + wrow + r) * 128 + col],     lo);
            __stcs((float2*)&out_vf[(size_t)(row0 + wrow + r + 8) * 128 + col], hi);
        }
    }

    // ========= Phase E: eh = relu(latent @ We1 + be1), N=128 ===============
    float ehA[16][4];
    zacc(ehA);
    mma_panel_g<8, 16, 8>(g_We1p, la, ehA, lane);
#pragma unroll
    for (int nt = 0; nt < 16; nt++) {
        int col = nt * 8 + 2 * c;
        float2 bb = *(const float2*)&be1[col];
        ehA[nt][0] = tf(fmaxf(ehA[nt][0] + bb.x, 0.f));
        ehA[nt][1] = tf(fmaxf(ehA[nt][1] + bb.y, 0.f));
        ehA[nt][2] = tf(fmaxf(ehA[nt][2] + bb.x, 0.f));
        ehA[nt][3] = tf(fmaxf(ehA[nt][3] + bb.y, 0.f));
        frag_to_a(ehA[nt], lane);
    }

    // ========= Phase F1: logits = eh @ blockdiag(We2) + be2, N=16 ==========
    {
        float lg[2][4];
        zacc(lg);
        mma_panel_g<16, 2, 4>(g_W2p, ehA, lg, lane);
#pragma unroll
        for (int nt = 0; nt < 2; nt++) {
            int col = nt * 8 + 2 * c;
            float bx = (col < 12)     ? be2[col]     : 0.f;
            float by = (col + 1 < 12) ? be2[col + 1] : 0.f;
            *(float2*)&sLg[(wrow + r) * 16 + col] =
                make_float2(lg[nt][0] + bx, lg[nt][1] + by);
            *(float2*)&sLg[(wrow + r + 8) * 16 + col] =
                make_float2(lg[nt][2] + bx, lg[nt][3] + by);
        }
    }
    __syncthreads();

    // ========= Phase F2: softmax + gated combine (thread=(row,e)) ==========
    {
        int row = tid >> 1, e = tid & 1;
        const float* lp = &sLg[row * 16 + e * 6];
        float lgs[6];
#pragma unroll
        for (int o = 0; o < 6; o++) lgs[o] = lp[o];
        float m = lgs[0];
#pragma unroll
        for (int o = 1; o < 6; o++) m = fmaxf(m, lgs[o]);
        float p[6], s = 0.f;
#pragma unroll
        for (int o = 0; o < 6; o++) { p[o] = __expf(lgs[o] - m); s += p[o]; }
        float inv = 1.f / s;
        float g = sG[tid];
        size_t gbase = ((size_t)(row0 + row) * 2 + e) * 6;
        float act[6];
#pragma unroll
        for (int o = 0; o < 6; o++) {
            float po = p[o] * inv;
            __stcs(&out_expout[gbase + o], po);
            act[o] = g * po;
        }
        // combine expert pair (adjacent lanes) and write action from e==0
#pragma unroll
        for (int o = 0; o < 6; o++)
            act[o] += __shfl_xor_sync(0xffffffffu, act[o], 1);
        if (e == 0) {
            size_t ab = (size_t)(row0 + row) * 6;
            __stcs(&out_action[ab + 0], act[0]);
            __stcs(&out_action[ab + 1], act[1]);
            __stcs(&out_action[ab + 2], act[2]);
            __stcs(&out_action[ab + 3], act[3]);
            __stcs(&out_action[ab + 4], act[4]);
            __stcs(&out_action[ab + 5], act[5]);
        }
    }
}

extern "C" void kernel_launch(void* const* d_in, const int* in_sizes, int n_in,
                              void* d_out, int out_size) {
    const float* feat    = (const float*)d_in[0];
    const float* noise   = (const float*)d_in[1];
    const float* Ws0     = (const float*)d_in[2];
    const float* bs0     = (const float*)d_in[3];
    const float* Ws1     = (const float*)d_in[4];
    const float* bs1     = (const float*)d_in[5];
    const float* Wv      = (const float*)d_in[6];
    const float* bv      = (const float*)d_in[7];
    const float* w_gate  = (const float*)d_in[8];
    const float* w_noise = (const float*)d_in[9];
    const float* We1     = (const float*)d_in[10];
    const float* be1     = (const float*)d_in[11];
    const float* We2     = (const float*)d_in[12];
    const float* be2     = (const float*)d_in[13];

    const int B = in_sizes[0] / 128;

    float* out        = (float*)d_out;
    float* out_action = out;                       // [B,6]
    float* out_vf     = out + (size_t)B * 6;       // [B,128]
    float* out_expout = out + (size_t)B * 134;     // [B,2,6]

    pack_weights<<<85, 256>>>(Ws0, Ws1, Wv, We1, w_gate, w_noise, We2);
    mlp_fused_kernel<<<B / ROWS, TPB>>>(
        feat, noise, bs0, bs1, bv, be1, be2,
        out_action, out_vf, out_expout);
}